// round 7
// baseline (speedup 1.0000x reference)
#include <cuda_runtime.h>
#include <math.h>
#include <stdint.h>

#define B_     128
#define HID_   512
#define NG_    2048
#define VOCAB_ 1000
#define VTOT_  3048
#define T_     256
#define GRIDP  128           // persistent grid: 32 clusters x 4
#define NTHR   256

#define OUT_H  (B_*T_*VOCAB_)
#define OUT_C  (OUT_H + B_*HID_)

// ---------------- device scratch ----------------
__device__ __align__(16) float g_E2[VOCAB_*NG_];     // [v][u][4]: i,f,g,o
__device__ __align__(16) float g_base[NG_*B_];       // col-major [gatecol][r]
__device__ __align__(16) float g_Gred[NG_*B_];       // fully reduced gates
__device__ __align__(16) float g_hhi[B_*HID_];       // tf32-hi of h
__device__ __align__(16) float g_hlo[B_*HID_];       // tf32-lo of h
__device__ unsigned long long g_pack[2][B_];
__device__ unsigned g_bar;

__device__ __forceinline__ float tf32_rd(float x){
  uint32_t u; asm("cvt.rna.tf32.f32 %0, %1;" : "=r"(u) : "f"(x));
  return __uint_as_float(u);
}
__device__ __forceinline__ unsigned fkey(float x){
  unsigned u = __float_as_uint(x);
  return (u & 0x80000000u) ? ~u : (u | 0x80000000u);
}
__device__ __forceinline__ void mma_tf32(float* d, const uint32_t* a, const uint32_t* b){
  asm volatile("mma.sync.aligned.m16n8k8.row.col.f32.tf32.tf32.f32 "
    "{%0,%1,%2,%3}, {%4,%5,%6,%7}, {%8,%9}, {%0,%1,%2,%3};"
    : "+f"(d[0]), "+f"(d[1]), "+f"(d[2]), "+f"(d[3])
    : "r"(a[0]), "r"(a[1]), "r"(a[2]), "r"(a[3]), "r"(b[0]), "r"(b[1]));
}
__device__ __forceinline__ uint32_t smem_u32(const void* p){
  uint32_t a;
  asm("{ .reg .u64 t; cvta.to.shared.u64 t, %1; cvt.u32.u64 %0, t; }" : "=r"(a) : "l"(p));
  return a;
}
__device__ __forceinline__ uint32_t mapa_u32(uint32_t addr, uint32_t rank){
  uint32_t r; asm("mapa.shared::cluster.u32 %0, %1, %2;" : "=r"(r) : "r"(addr), "r"(rank));
  return r;
}
__device__ __forceinline__ void st_cluster_v2(uint32_t addr, float x, float y){
  asm volatile("st.shared::cluster.v2.f32 [%0], {%1, %2};" :: "r"(addr), "f"(x), "f"(y) : "memory");
}
__device__ __forceinline__ uint32_t ctarank(){
  uint32_t r; asm("mov.u32 %0, %%cluster_ctarank;" : "=r"(r)); return r;
}
#define CLUSTER_SYNC() do { \
  asm volatile("barrier.cluster.arrive.aligned;" ::: "memory"); \
  asm volatile("barrier.cluster.wait.aligned;" ::: "memory"); } while(0)
#define DOT4(acc, a, b) acc = fmaf((a).x,(b).x, fmaf((a).y,(b).y, fmaf((a).z,(b).z, fmaf((a).w,(b).w,(acc)))))

// ---------------- prologue 1: E2 = embed @ Wih_emb^T ----------------
__global__ void __launch_bounds__(256) k_E(const float* __restrict__ emb,
                                           const float* __restrict__ Wih){
  __shared__ float As[16*68], Bs[16*68];
  const int tid = threadIdx.x;
  const int tx = tid & 15, ty = tid >> 4;
  const int c0 = blockIdx.x * 64, v0 = blockIdx.y * 64;
  float acc[4][4];
#pragma unroll
  for (int i=0;i<4;++i)
#pragma unroll
    for (int j=0;j<4;++j) acc[i][j] = 0.f;

  const int rr = tid >> 2, kq = tid & 3;
  for (int kc = 0; kc < 512; kc += 16){
    int v = v0 + rr; if (v >= VOCAB_) v = VOCAB_ - 1;
    float4 a = __ldg((const float4*)(emb + (size_t)v*512 + kc + 4*kq));
    As[(4*kq+0)*68 + rr] = a.x; As[(4*kq+1)*68 + rr] = a.y;
    As[(4*kq+2)*68 + rr] = a.z; As[(4*kq+3)*68 + rr] = a.w;
    int g = c0 + rr;
    float4 b = __ldg((const float4*)(Wih + (size_t)g*1024 + 512 + kc + 4*kq));
    Bs[(4*kq+0)*68 + rr] = b.x; Bs[(4*kq+1)*68 + rr] = b.y;
    Bs[(4*kq+2)*68 + rr] = b.z; Bs[(4*kq+3)*68 + rr] = b.w;
    __syncthreads();
#pragma unroll
    for (int k = 0; k < 16; ++k){
      float4 av = *(const float4*)&As[k*68 + ty*4];
      float4 bv = *(const float4*)&Bs[k*68 + tx*4];
      float ai[4] = {av.x, av.y, av.z, av.w};
      float bj[4] = {bv.x, bv.y, bv.z, bv.w};
#pragma unroll
      for (int i=0;i<4;++i)
#pragma unroll
        for (int j=0;j<4;++j) acc[i][j] = fmaf(ai[i], bj[j], acc[i][j]);
    }
    __syncthreads();
  }
  for (int i=0;i<4;++i){
    int v = v0 + ty*4 + i;
    if (v < VOCAB_)
      for (int j=0;j<4;++j){
        int c = c0 + tx*4 + j;
        g_E2[((size_t)v*512 + (c & 511))*4 + (c >> 9)] = acc[i][j];
      }
  }
}

// ---------------- prologue 2: g_base (exact fp32) ----------------
__global__ void __launch_bounds__(256) k_base(const float* __restrict__ Wih,
                                              const float* __restrict__ bih,
                                              const float* __restrict__ bhh,
                                              const float* __restrict__ ctx){
  __shared__ float xs[128*68], wsm[16*68];
  const int tid = threadIdx.x, blk = blockIdx.x;
  const int tx = tid & 7, ty = tid >> 3, r0 = ty*4;
  const int gc0 = blk*16 + 2*tx, gc1 = gc0 + 1;
  float acc[4][2];
#pragma unroll
  for (int i=0;i<4;++i){ acc[i][0]=0.f; acc[i][1]=0.f; }

  for (int kc = 0; kc < 512; kc += 64){
    for (int p = 0; p < 8; ++p){
      int lin = tid + p*256; int r = lin >> 4, kq2 = lin & 15;
      *(float4*)&xs[r*68 + 4*kq2] = __ldg((const float4*)(ctx + (size_t)r*512 + kc + 4*kq2));
    }
    { int cc = tid >> 4, kq2 = tid & 15;
      *(float4*)&wsm[cc*68 + 4*kq2] =
        __ldg((const float4*)(Wih + (size_t)(blk*16+cc)*1024 + kc + 4*kq2)); }
    __syncthreads();
#pragma unroll
    for (int k4 = 0; k4 < 16; ++k4){
      int kl = 4*k4;
      float4 w0 = *(const float4*)&wsm[(2*tx)*68 + kl];
      float4 w1 = *(const float4*)&wsm[(2*tx+1)*68 + kl];
#pragma unroll
      for (int i=0;i<4;++i){
        float4 h4 = *(const float4*)&xs[(r0+i)*68 + kl];
        DOT4(acc[i][0], h4, w0); DOT4(acc[i][1], h4, w1);
      }
    }
    __syncthreads();
  }
  float bb0 = __ldg(bih+gc0) + __ldg(bhh+gc0);
  float bb1 = __ldg(bih+gc1) + __ldg(bhh+gc1);
  for (int i=0;i<4;++i){
    g_base[(size_t)gc0*B_ + r0+i] = acc[i][0] + bb0;
    g_base[(size_t)gc1*B_ + r0+i] = acc[i][1] + bb1;
  }
}

// ---------------- prologue 3 ----------------
__global__ void k_init(const float* __restrict__ ctx, const int* __restrict__ sid){
  int idx = blockIdx.x*blockDim.x + threadIdx.x;
  if (idx < B_*HID_){
    float x = ctx[idx];
    float hi = tf32_rd(x);
    g_hhi[idx] = hi;
    g_hlo[idx] = tf32_rd(x - hi);
  }
  if (idx < B_){
    g_pack[0][idx] = (unsigned long long)(unsigned)((VOCAB_-1) - *sid);
    g_pack[1][idx] = 0ull;
  }
  if (idx == 0) g_bar = 0u;
}

// ---------------- grid barrier ----------------
__device__ __forceinline__ void gbar(unsigned target){
  __syncthreads();
  if (threadIdx.x == 0){
    __threadfence();
    atomicAdd(&g_bar, 1u);
    while (*(volatile unsigned*)&g_bar < target) { }
    __threadfence();
  }
  __syncthreads();
}

// ---------------- persistent kernel ----------------
// smem float offsets
#define SA_H   0                 // A hi frag-packed: 96*128 = 12288
#define SA_L   12288             // A lo
#define SB_H   24576             // B hi tile [128][68] = 8704
#define SB_L   33280             // B lo tile
#define S_RED  41984             // redbuf [4][24][128] = 12288
#define S_TOK  54272             // 128 ints
#define SMW_   54400             // 217600 bytes

__global__ void __launch_bounds__(NTHR, 1) __cluster_dims__(4, 1, 1)
k_persist(const float* __restrict__ Whh, const float* __restrict__ Wout,
          const float* __restrict__ bout, float* __restrict__ out){
  extern __shared__ float sm[];
  float* Ah = sm + SA_H;
  float* Al = sm + SA_L;
  float* Bh = sm + SB_H;
  float* Bl = sm + SB_L;
  float* red = sm + S_RED;
  int*   toks = (int*)(sm + S_TOK);

  const int cta = blockIdx.x, tid = threadIdx.x;
  const int wid = tid >> 5, lane = tid & 31;
  const int mtile = cta >> 2;
  const int kidx = (int)ctarank();          // rank within cluster = K-split index
  const int kbase = kidx*128;
  const int wm = wid >> 2, wn = wid & 3;    // warp tile 48M x 32N
  const uint32_t red_base = smem_u32(red);

  // ---- stage A (weights hi/lo, fragment-packed) once ----
  for (int lin = tid; lin < 3072; lin += NTHR){
    int ml = lin >> 5, q = lin & 31;
    int gm = mtile*96 + ml;
    float4 w = make_float4(0.f,0.f,0.f,0.f);
    if (gm < NG_)        w = __ldg((const float4*)(Whh  + (size_t)gm*HID_ + kbase + q*4));
    else if (gm < VTOT_) w = __ldg((const float4*)(Wout + (size_t)(gm-NG_)*HID_ + kbase + q*4));
    int f = (ml >> 4)*16 + (q >> 1);
    int ofs = f*128 + (ml & 7)*16 + ((ml >> 3) & 1) + 2*(q & 1);
    float hi;
    hi = tf32_rd(w.x); Ah[ofs+ 0] = hi; Al[ofs+ 0] = tf32_rd(w.x - hi);
    hi = tf32_rd(w.y); Ah[ofs+ 4] = hi; Al[ofs+ 4] = tf32_rd(w.y - hi);
    hi = tf32_rd(w.z); Ah[ofs+ 8] = hi; Al[ofs+ 8] = tf32_rd(w.z - hi);
    hi = tf32_rd(w.w); Ah[ofs+12] = hi; Al[ofs+12] = tf32_rd(w.w - hi);
  }
  __syncthreads();

  float cr0 = 0.f, cr1 = 0.f;
  const int yi0 = cta*NTHR + tid;           // 0..32767
  const int yi1 = yi0 + GRIDP*NTHR;         // 32768..65535

  unsigned bt = 0;
  for (int m = 0; m <= T_; ++m){
    // ================ phase X: 3xTF32 mma.sync ================
    float acc[12][4];
#pragma unroll
    for (int i=0;i<12;++i)
#pragma unroll
      for (int j=0;j<4;++j) acc[i][j] = 0.f;

    for (int ch = 0; ch < 2; ++ch){
      for (int lin = tid; lin < 2048; lin += NTHR){
        int r = lin >> 4, q = lin & 15;
        float4 h = __ldcg((const float4*)(g_hhi + (size_t)r*HID_ + kbase + ch*64 + q*4));
        float4 l = __ldcg((const float4*)(g_hlo + (size_t)r*HID_ + kbase + ch*64 + q*4));
        *(float4*)&Bh[r*68 + q*4] = h;
        *(float4*)&Bl[r*68 + q*4] = l;
      }
      __syncthreads();
#pragma unroll 2
      for (int ks = 0; ks < 8; ++ks){
        uint32_t bh[4][2], bl[4][2];
        int kk = ks*8 + (lane & 3);
#pragma unroll
        for (int ni = 0; ni < 4; ++ni){
          int n = wn*32 + ni*8 + (lane >> 2);
          bh[ni][0] = __float_as_uint(Bh[n*68 + kk]);
          bh[ni][1] = __float_as_uint(Bh[n*68 + kk + 4]);
          bl[ni][0] = __float_as_uint(Bl[n*68 + kk]);
          bl[ni][1] = __float_as_uint(Bl[n*68 + kk + 4]);
        }
#pragma unroll
        for (int mi = 0; mi < 3; ++mi){
          int f = (wm*3 + mi)*16 + ch*8 + ks;
          uint4 ahv = *(const uint4*)&Ah[(f*32 + lane)*4];
          uint4 alv = *(const uint4*)&Al[(f*32 + lane)*4];
          const uint32_t* ah = (const uint32_t*)&ahv;
          const uint32_t* al = (const uint32_t*)&alv;
#pragma unroll
          for (int ni = 0; ni < 4; ++ni){
            mma_tf32(acc[mi*4+ni], ah, bh[ni]);
            mma_tf32(acc[mi*4+ni], ah, bl[ni]);
            mma_tf32(acc[mi*4+ni], al, bh[ni]);
          }
        }
      }
      __syncthreads();
    }

    // ---- push partials to row-owner CTA in cluster (DSMEM) ----
#pragma unroll
    for (int mi = 0; mi < 3; ++mi){
#pragma unroll
      for (int ni = 0; ni < 4; ++ni){
        int col = wn*32 + ni*8 + (lane & 3)*2;
#pragma unroll
        for (int hh = 0; hh < 2; ++hh){
          int row = wm*48 + mi*16 + (lane >> 2) + hh*8;
          int q = row/24, rl = row - q*24;
          float x = acc[mi*4+ni][hh*2+0], y = acc[mi*4+ni][hh*2+1];
          uint32_t off = (uint32_t)(((kidx*24 + rl)*128 + col)*4);
          if (q == kidx){
            *(float2*)((char*)red + off) = make_float2(x, y);
          } else {
            st_cluster_v2(mapa_u32(red_base + off, (uint32_t)q), x, y);
          }
        }
      }
    }
    CLUSTER_SYNC();

    // ---- reduce own 24 rows: Gred (gates) / logits + out (vocab) ----
    for (int it = tid; it < 24*128; it += NTHR){
      int rl = it >> 7, r = it & 127;
      float s = red[(0*24+rl)*128 + r] + red[(1*24+rl)*128 + r]
              + red[(2*24+rl)*128 + r] + red[(3*24+rl)*128 + r];
      int gm = mtile*96 + kidx*24 + rl;
      if (gm < NG_){
        g_Gred[(size_t)gm*B_ + r] = g_base[(size_t)gm*B_ + r] + s;
      } else if (gm < VTOT_){
        int v = gm - NG_;
        float logit = s + __ldg(bout + v);
        if (m >= 1) out[((size_t)r*T_ + (m-1))*VOCAB_ + v] = logit;
        red[rl*128 + r] = logit;          // stash for argmax (slot 0 reuse)
      }
    }
    __syncthreads();
    if (m >= 1 && m < T_){
      int r = tid & 127, hf = tid >> 7;
      unsigned long long best = 0ull;
      for (int rl = hf*12; rl < hf*12 + 12; ++rl){
        int gm = mtile*96 + kidx*24 + rl;
        if (gm >= NG_ && gm < VTOT_){
          unsigned long long pk =
            ((unsigned long long)fkey(red[rl*128 + r]) << 32)
            | (unsigned)(VOCAB_-1 - (gm - NG_));
          if (pk > best) best = pk;
        }
      }
      if (best) atomicMax(&g_pack[m & 1][r], best);
    }

    bt += GRIDP; gbar(bt);
    if (m == T_) break;

    // ================ phase Y: E-gather + LSTM cell (fast math) ========
    {
      if (tid < B_){
        unsigned long long p = __ldcg(&g_pack[m & 1][tid]);
        toks[tid] = (VOCAB_-1) - (int)(unsigned)(p & 0xffffffffull);
      }
      __syncthreads();
#pragma unroll
      for (int qq = 0; qq < 2; ++qq){
        int idx = qq ? yi1 : yi0;
        int r = idx & 127, u = idx >> 7;
        int tok = toks[r];
        float4 ev = __ldg((const float4*)&g_E2[((size_t)tok*HID_ + u)*4]);
        float gi = __ldcg(&g_Gred[(size_t)u*B_ + r]) + ev.x;
        float gf = __ldcg(&g_Gred[(size_t)(512+u)*B_ + r]) + ev.y;
        float gg = __ldcg(&g_Gred[(size_t)(1024+u)*B_ + r]) + ev.z;
        float go = __ldcg(&g_Gred[(size_t)(1536+u)*B_ + r]) + ev.w;
        float e;
        e = __expf(-gi);     gi = __fdividef(1.f, 1.f + e);
        e = __expf(-gf);     gf = __fdividef(1.f, 1.f + e);
        e = __expf(2.f*gg);  gg = 1.f - __fdividef(2.f, e + 1.f);
        e = __expf(-go);     go = __fdividef(1.f, 1.f + e);
        float cold = qq ? cr1 : cr0;
        float cn = fmaf(gf, cold, gi*gg);
        if (qq) cr1 = cn; else cr0 = cn;
        e = __expf(2.f*cn);
        float hn = go * (1.f - __fdividef(2.f, e + 1.f));
        float hi = tf32_rd(hn);
        g_hhi[(size_t)r*HID_ + u] = hi;
        g_hlo[(size_t)r*HID_ + u] = tf32_rd(hn - hi);
        if (m == T_-1){
          out[OUT_H + (size_t)r*HID_ + u] = hn;
          out[OUT_C + (size_t)r*HID_ + u] = cn;
        }
      }
      if (yi0 < B_) g_pack[(m+1) & 1][yi0] = 0ull;
    }
    bt += GRIDP; gbar(bt);
  }
}

// ---------------- launch ----------------
extern "C" void kernel_launch(void* const* d_in, const int* in_sizes, int n_in,
                              void* d_out, int out_size){
  const float* ctx  = (const float*)d_in[0];
  const float* emb  = (const float*)d_in[1];
  const float* Wih  = (const float*)d_in[2];
  const float* bih  = (const float*)d_in[3];
  const float* Whh  = (const float*)d_in[4];
  const float* bhh  = (const float*)d_in[5];
  const float* Wout = (const float*)d_in[6];
  const float* bout = (const float*)d_in[7];
  const int*   sid  = (const int*)d_in[8];
  float* out = (float*)d_out;

  cudaFuncSetAttribute(k_persist, cudaFuncAttributeMaxDynamicSharedMemorySize,
                       SMW_ * 4);

  dim3 gE(32, 16);
  k_E<<<gE, 256>>>(emb, Wih);
  k_base<<<128, 256>>>(Wih, bih, bhh, ctx);
  k_init<<<256, 256>>>(ctx, sid);
  k_persist<<<GRIDP, NTHR, SMW_ * 4>>>(Whh, Wout, bout, out);
}

// round 8
// speedup vs baseline: 1.1718x; 1.1718x over previous
#include <cuda_runtime.h>
#include <math.h>
#include <stdint.h>

#define B_     128
#define HID_   512
#define NG_    2048
#define VOCAB_ 1000
#define VTOT_  3048
#define ROWS_  3072
#define T_     256
#define GRID_  148
#define NTHR   512
#define XCTAS  128           // 32 M-tiles (96 rows) x 4 K-splits

#define OUT_H  (B_*T_*VOCAB_)
#define OUT_C  (OUT_H + B_*HID_)

// ---------------- device scratch ----------------
__device__ __align__(16) float g_E2[VOCAB_*NG_];     // [v][u][4]: i,f,g,o
__device__ __align__(16) float g_base[NG_*B_];       // col-major [gatecol][r]
__device__ __align__(16) float g_Gred[NG_*B_];       // fully reduced gates
__device__ __align__(16) float g_hhi[B_*HID_];       // tf32-hi of h
__device__ __align__(16) float g_hlo[B_*HID_];       // tf32-lo of h
__device__ __align__(16) float g_part[4*ROWS_*B_];   // [k][row][r]
__device__ unsigned long long g_pack[2][B_];
__device__ unsigned g_bar;

__device__ __forceinline__ float tf32_rd(float x){
  uint32_t u; asm("cvt.rna.tf32.f32 %0, %1;" : "=r"(u) : "f"(x));
  return __uint_as_float(u);
}
__device__ __forceinline__ unsigned fkey(float x){
  unsigned u = __float_as_uint(x);
  return (u & 0x80000000u) ? ~u : (u | 0x80000000u);
}
__device__ __forceinline__ void mma_tf32(float* d, const uint32_t* a, const uint32_t* b){
  asm volatile("mma.sync.aligned.m16n8k8.row.col.f32.tf32.tf32.f32 "
    "{%0,%1,%2,%3}, {%4,%5,%6,%7}, {%8,%9}, {%0,%1,%2,%3};"
    : "+f"(d[0]), "+f"(d[1]), "+f"(d[2]), "+f"(d[3])
    : "r"(a[0]), "r"(a[1]), "r"(a[2]), "r"(a[3]), "r"(b[0]), "r"(b[1]));
}
#define DOT4(acc, a, b) acc = fmaf((a).x,(b).x, fmaf((a).y,(b).y, fmaf((a).z,(b).z, fmaf((a).w,(b).w,(acc)))))

// ---------------- prologue 1: E2 = embed @ Wih_emb^T ----------------
__global__ void __launch_bounds__(256) k_E(const float* __restrict__ emb,
                                           const float* __restrict__ Wih){
  __shared__ float As[16*68], Bs[16*68];
  const int tid = threadIdx.x;
  const int tx = tid & 15, ty = tid >> 4;
  const int c0 = blockIdx.x * 64, v0 = blockIdx.y * 64;
  float acc[4][4];
#pragma unroll
  for (int i=0;i<4;++i)
#pragma unroll
    for (int j=0;j<4;++j) acc[i][j] = 0.f;

  const int rr = tid >> 2, kq = tid & 3;
  for (int kc = 0; kc < 512; kc += 16){
    int v = v0 + rr; if (v >= VOCAB_) v = VOCAB_ - 1;
    float4 a = __ldg((const float4*)(emb + (size_t)v*512 + kc + 4*kq));
    As[(4*kq+0)*68 + rr] = a.x; As[(4*kq+1)*68 + rr] = a.y;
    As[(4*kq+2)*68 + rr] = a.z; As[(4*kq+3)*68 + rr] = a.w;
    int g = c0 + rr;
    float4 b = __ldg((const float4*)(Wih + (size_t)g*1024 + 512 + kc + 4*kq));
    Bs[(4*kq+0)*68 + rr] = b.x; Bs[(4*kq+1)*68 + rr] = b.y;
    Bs[(4*kq+2)*68 + rr] = b.z; Bs[(4*kq+3)*68 + rr] = b.w;
    __syncthreads();
#pragma unroll
    for (int k = 0; k < 16; ++k){
      float4 av = *(const float4*)&As[k*68 + ty*4];
      float4 bv = *(const float4*)&Bs[k*68 + tx*4];
      float ai[4] = {av.x, av.y, av.z, av.w};
      float bj[4] = {bv.x, bv.y, bv.z, bv.w};
#pragma unroll
      for (int i=0;i<4;++i)
#pragma unroll
        for (int j=0;j<4;++j) acc[i][j] = fmaf(ai[i], bj[j], acc[i][j]);
    }
    __syncthreads();
  }
  for (int i=0;i<4;++i){
    int v = v0 + ty*4 + i;
    if (v < VOCAB_)
      for (int j=0;j<4;++j){
        int c = c0 + tx*4 + j;
        g_E2[((size_t)v*512 + (c & 511))*4 + (c >> 9)] = acc[i][j];
      }
  }
}

// ---------------- prologue 2: g_base (exact fp32) ----------------
__global__ void __launch_bounds__(256) k_base(const float* __restrict__ Wih,
                                              const float* __restrict__ bih,
                                              const float* __restrict__ bhh,
                                              const float* __restrict__ ctx){
  __shared__ float xs[128*68], wsm[16*68];
  const int tid = threadIdx.x, blk = blockIdx.x;
  const int tx = tid & 7, ty = tid >> 3, r0 = ty*4;
  const int gc0 = blk*16 + 2*tx, gc1 = gc0 + 1;
  float acc[4][2];
#pragma unroll
  for (int i=0;i<4;++i){ acc[i][0]=0.f; acc[i][1]=0.f; }

  for (int kc = 0; kc < 512; kc += 64){
    for (int p = 0; p < 8; ++p){
      int lin = tid + p*256; int r = lin >> 4, kq2 = lin & 15;
      *(float4*)&xs[r*68 + 4*kq2] = __ldg((const float4*)(ctx + (size_t)r*512 + kc + 4*kq2));
    }
    { int cc = tid >> 4, kq2 = tid & 15;
      *(float4*)&wsm[cc*68 + 4*kq2] =
        __ldg((const float4*)(Wih + (size_t)(blk*16+cc)*1024 + kc + 4*kq2)); }
    __syncthreads();
#pragma unroll
    for (int k4 = 0; k4 < 16; ++k4){
      int kl = 4*k4;
      float4 w0 = *(const float4*)&wsm[(2*tx)*68 + kl];
      float4 w1 = *(const float4*)&wsm[(2*tx+1)*68 + kl];
#pragma unroll
      for (int i=0;i<4;++i){
        float4 h4 = *(const float4*)&xs[(r0+i)*68 + kl];
        DOT4(acc[i][0], h4, w0); DOT4(acc[i][1], h4, w1);
      }
    }
    __syncthreads();
  }
  float bb0 = __ldg(bih+gc0) + __ldg(bhh+gc0);
  float bb1 = __ldg(bih+gc1) + __ldg(bhh+gc1);
  for (int i=0;i<4;++i){
    g_base[(size_t)gc0*B_ + r0+i] = acc[i][0] + bb0;
    g_base[(size_t)gc1*B_ + r0+i] = acc[i][1] + bb1;
  }
}

// ---------------- prologue 3 ----------------
__global__ void k_init(const float* __restrict__ ctx, const int* __restrict__ sid){
  int idx = blockIdx.x*blockDim.x + threadIdx.x;
  if (idx < B_*HID_){
    float x = ctx[idx];
    float hi = tf32_rd(x);
    g_hhi[idx] = hi;
    g_hlo[idx] = tf32_rd(x - hi);
  }
  if (idx < B_){
    g_pack[0][idx] = (unsigned long long)(unsigned)((VOCAB_-1) - *sid);
    g_pack[1][idx] = 0ull;
  }
  if (idx == 0) g_bar = 0u;
}

// ---------------- grid barrier ----------------
__device__ __forceinline__ void gbar(unsigned target){
  __syncthreads();
  if (threadIdx.x == 0){
    __threadfence();
    atomicAdd(&g_bar, 1u);
    while (*(volatile unsigned*)&g_bar < target) { }
    __threadfence();
  }
  __syncthreads();
}

// ---------------- persistent kernel ----------------
// smem float offsets
#define SA_H   0                 // A hi frag-packed: 96*128 = 12288
#define SA_L   12288             // A lo
#define SB_H   24576             // B hi tile [128][68] = 8704
#define SB_L   33280             // B lo tile
#define S_TOK  41984             // 128 ints
#define S_LS   42112             // 8*128 floats
#define SMW_   43136             // 172544 bytes

__global__ void __launch_bounds__(NTHR, 1)
k_persist(const float* __restrict__ Whh, const float* __restrict__ Wout,
          const float* __restrict__ bout, float* __restrict__ out){
  extern __shared__ float sm[];
  float* Ah = sm + SA_H;
  float* Al = sm + SA_L;
  float* Bh = sm + SB_H;
  float* Bl = sm + SB_L;
  int*   toks = (int*)(sm + S_TOK);
  float* Ls = sm + S_LS;

  const int cta = blockIdx.x, tid = threadIdx.x;
  const int wid = tid >> 5, lane = tid & 31;
  const bool isX = (cta < XCTAS);
  const int mtile = cta >> 2, kidx = cta & 3, kbase = kidx*128;
  const int wm = wid >> 3, wn = wid & 7;          // warp tile 48M x 16N

  // ---- stage A (weights hi/lo, fragment-packed) once ----
  if (isX){
    for (int lin = tid; lin < 3072; lin += NTHR){
      int ml = lin >> 5, q = lin & 31;
      int gm = mtile*96 + ml;
      float4 w = make_float4(0.f,0.f,0.f,0.f);
      if (gm < NG_)        w = __ldg((const float4*)(Whh  + (size_t)gm*HID_ + kbase + q*4));
      else if (gm < VTOT_) w = __ldg((const float4*)(Wout + (size_t)(gm-NG_)*HID_ + kbase + q*4));
      int f = (ml >> 4)*16 + (q >> 1);
      int ofs = f*128 + (ml & 7)*16 + ((ml >> 3) & 1) + 2*(q & 1);
      float hi;
      hi = tf32_rd(w.x); Ah[ofs+ 0] = hi; Al[ofs+ 0] = tf32_rd(w.x - hi);
      hi = tf32_rd(w.y); Ah[ofs+ 4] = hi; Al[ofs+ 4] = tf32_rd(w.y - hi);
      hi = tf32_rd(w.z); Ah[ofs+ 8] = hi; Al[ofs+ 8] = tf32_rd(w.z - hi);
      hi = tf32_rd(w.w); Ah[ofs+12] = hi; Al[ofs+12] = tf32_rd(w.w - hi);
    }
  }
  __syncthreads();

  float cr = 0.f;
  const int yi = cta*NTHR + tid;                  // single-pass Yc index

  unsigned bt = 0;
  for (int m = 0; m <= T_; ++m){
    // ================ phase X: 3xTF32 mma.sync ================
    if (isX){
      float acc[6][4];
#pragma unroll
      for (int i=0;i<6;++i)
#pragma unroll
        for (int j=0;j<4;++j) acc[i][j] = 0.f;

      for (int ch = 0; ch < 2; ++ch){
        // stage B chunk (64 K-floats, hi+lo), conflict-free
        for (int lin = tid; lin < 2048; lin += NTHR){
          int r = lin >> 4, q = lin & 15;
          float4 h = __ldcg((const float4*)(g_hhi + (size_t)r*HID_ + kbase + ch*64 + q*4));
          float4 l = __ldcg((const float4*)(g_hlo + (size_t)r*HID_ + kbase + ch*64 + q*4));
          *(float4*)&Bh[r*68 + q*4] = h;
          *(float4*)&Bl[r*68 + q*4] = l;
        }
        __syncthreads();
#pragma unroll 2
        for (int ks = 0; ks < 8; ++ks){
          uint32_t bh[2][2], bl[2][2];
          int kk = ks*8 + (lane & 3);
#pragma unroll
          for (int ni = 0; ni < 2; ++ni){
            int n = wn*16 + ni*8 + (lane >> 2);
            bh[ni][0] = __float_as_uint(Bh[n*68 + kk]);
            bh[ni][1] = __float_as_uint(Bh[n*68 + kk + 4]);
            bl[ni][0] = __float_as_uint(Bl[n*68 + kk]);
            bl[ni][1] = __float_as_uint(Bl[n*68 + kk + 4]);
          }
#pragma unroll
          for (int mi = 0; mi < 3; ++mi){
            int f = (wm*3 + mi)*16 + ch*8 + ks;
            uint4 ahv = *(const uint4*)&Ah[(f*32 + lane)*4];
            uint4 alv = *(const uint4*)&Al[(f*32 + lane)*4];
            const uint32_t* ah = (const uint32_t*)&ahv;
            const uint32_t* al = (const uint32_t*)&alv;
#pragma unroll
            for (int ni = 0; ni < 2; ++ni){
              mma_tf32(acc[mi*2+ni], ah, bh[ni]);
              mma_tf32(acc[mi*2+ni], ah, bl[ni]);
              mma_tf32(acc[mi*2+ni], al, bh[ni]);
            }
          }
        }
        __syncthreads();
      }
      // store D partials
#pragma unroll
      for (int mi = 0; mi < 3; ++mi){
#pragma unroll
        for (int ni = 0; ni < 2; ++ni){
          int row0 = mtile*96 + wm*48 + mi*16 + (lane >> 2);
          int col = wn*16 + ni*8 + (lane & 3)*2;
          float* dst = g_part + ((size_t)kidx*ROWS_ + row0)*B_ + col;
          *(float2*)dst = make_float2(acc[mi*2+ni][0], acc[mi*2+ni][1]);
          *(float2*)(dst + 8*B_) = make_float2(acc[mi*2+ni][2], acc[mi*2+ni][3]);
        }
      }
    }
    bt += GRID_; gbar(bt);

    // ================ phase Yv: gate-reduce + vocab reduce + argmax ====
    if (m < T_){
      for (int lin = tid; lin < 14*128; lin += NTHR){
        int cl = cta*14 + (lin >> 7);
        if (cl < NG_){
          int r = lin & 127;
          float s = g_base[(size_t)cl*B_ + r];
          s += __ldcg(&g_part[(size_t)cl*B_ + r]);
          s += __ldcg(&g_part[((size_t)ROWS_ + cl)*B_ + r]);
          s += __ldcg(&g_part[((size_t)2*ROWS_ + cl)*B_ + r]);
          s += __ldcg(&g_part[((size_t)3*ROWS_ + cl)*B_ + r]);
          g_Gred[(size_t)cl*B_ + r] = s;
        }
      }
    }
    if (m >= 1){
      const int v0 = cta*7;
      if (wid < 7){
        int v = v0 + wid;
        if (v < VOCAB_){
          float bo = __ldg(bout + v);
          const float* p = g_part + (size_t)(NG_ + v)*B_;
#pragma unroll
          for (int rq = 0; rq < 4; ++rq){
            int r = rq*32 + lane;
            float sum = bo + __ldcg(p + r)
                      + __ldcg(p + (size_t)ROWS_*B_ + r)
                      + __ldcg(p + (size_t)2*ROWS_*B_ + r)
                      + __ldcg(p + (size_t)3*ROWS_*B_ + r);
            Ls[wid*128 + r] = sum;
          }
        }
      }
      __syncthreads();
      for (int it = tid; it < 128*8; it += NTHR){
        int r = it >> 3, vl = it & 7;
        int v = v0 + vl;
        if (vl < 7 && v < VOCAB_)
          out[((size_t)r*T_ + (m-1))*VOCAB_ + v] = Ls[vl*128 + r];
      }
      if (m < T_ && tid < 128){
        int r = tid;
        unsigned long long best = 0ull;
        for (int vl = 0; vl < 7; ++vl){
          int v = v0 + vl;
          if (v < VOCAB_){
            unsigned long long pk = ((unsigned long long)fkey(Ls[vl*128 + r]) << 32)
                                  | (unsigned)(VOCAB_-1 - v);
            if (pk > best) best = pk;
          }
        }
        if (best) atomicMax(&g_pack[m & 1][r], best);
      }
      __syncthreads();
    }
    if (m == T_) break;
    bt += GRID_; gbar(bt);

    // ================ phase Yc: E-gather + LSTM cell ================
    {
      if (tid < B_){
        unsigned long long p = __ldcg(&g_pack[m & 1][tid]);
        toks[tid] = (VOCAB_-1) - (int)(unsigned)(p & 0xffffffffull);
      }
      __syncthreads();
      if (yi < B_*HID_){
        int r = yi & 127, u = yi >> 7;
        int tok = toks[r];
        float4 ev = __ldg((const float4*)&g_E2[((size_t)tok*HID_ + u)*4]);
        float gi = __ldcg(&g_Gred[(size_t)u*B_ + r]) + ev.x;
        float gf = __ldcg(&g_Gred[(size_t)(512+u)*B_ + r]) + ev.y;
        float gg = __ldcg(&g_Gred[(size_t)(1024+u)*B_ + r]) + ev.z;
        float go = __ldcg(&g_Gred[(size_t)(1536+u)*B_ + r]) + ev.w;
        gi = 1.f/(1.f + expf(-gi));
        gf = 1.f/(1.f + expf(-gf));
        gg = tanhf(gg);
        go = 1.f/(1.f + expf(-go));
        float cn = fmaf(gf, cr, gi*gg);
        cr = cn;
        float hn = go * tanhf(cn);
        float hi = tf32_rd(hn);
        g_hhi[(size_t)r*HID_ + u] = hi;
        g_hlo[(size_t)r*HID_ + u] = tf32_rd(hn - hi);
        if (m == T_-1){
          out[OUT_H + (size_t)r*HID_ + u] = hn;
          out[OUT_C + (size_t)r*HID_ + u] = cn;
        }
      }
      if (yi < B_) g_pack[(m+1) & 1][yi] = 0ull;
    }
    bt += GRID_; gbar(bt);
  }
}

// ---------------- launch ----------------
extern "C" void kernel_launch(void* const* d_in, const int* in_sizes, int n_in,
                              void* d_out, int out_size){
  const float* ctx  = (const float*)d_in[0];
  const float* emb  = (const float*)d_in[1];
  const float* Wih  = (const float*)d_in[2];
  const float* bih  = (const float*)d_in[3];
  const float* Whh  = (const float*)d_in[4];
  const float* bhh  = (const float*)d_in[5];
  const float* Wout = (const float*)d_in[6];
  const float* bout = (const float*)d_in[7];
  const int*   sid  = (const int*)d_in[8];
  float* out = (float*)d_out;

  cudaFuncSetAttribute(k_persist, cudaFuncAttributeMaxDynamicSharedMemorySize,
                       SMW_ * 4);

  dim3 gE(32, 16);
  k_E<<<gE, 256>>>(emb, Wih);
  k_base<<<128, 256>>>(Wih, bih, bhh, ctx);
  k_init<<<256, 256>>>(ctx, sid);
  k_persist<<<GRID_, NTHR, SMW_ * 4>>>(Whh, Wout, bout, out);
}

// round 9
// speedup vs baseline: 1.2617x; 1.0767x over previous
#include <cuda_runtime.h>
#include <math.h>
#include <stdint.h>

#define B_     128
#define HID_   512
#define NG_    2048
#define VOCAB_ 1000
#define VTOT_  3048
#define ROWS_  3072
#define T_     256
#define GRID_  148
#define NTHR   256
#define XCTAS  128           // 32 M-tiles (96 rows) x 4 K-splits

#define OUT_H  (B_*T_*VOCAB_)
#define OUT_C  (OUT_H + B_*HID_)

// ---------------- device scratch ----------------
__device__ __align__(16) float g_E2[VOCAB_*NG_];     // [v][u][4]: i,f,g,o
__device__ __align__(16) float g_base[NG_*B_];       // col-major [gatecol][r]
__device__ __align__(16) float g_hhi[B_*HID_];       // tf32-hi of h
__device__ __align__(16) float g_hlo[B_*HID_];       // tf32-lo of h
__device__ __align__(16) float g_part[4*ROWS_*B_];   // [k][row][r]
__device__ unsigned long long g_pack[2][B_];
__device__ unsigned g_done[2][B_];
__device__ unsigned g_bar;

__device__ __forceinline__ float tf32_rd(float x){
  uint32_t u; asm("cvt.rna.tf32.f32 %0, %1;" : "=r"(u) : "f"(x));
  return __uint_as_float(u);
}
__device__ __forceinline__ unsigned fkey(float x){
  unsigned u = __float_as_uint(x);
  return (u & 0x80000000u) ? ~u : (u | 0x80000000u);
}
__device__ __forceinline__ void mma_tf32(float* d, const uint32_t* a, const uint32_t* b){
  asm volatile("mma.sync.aligned.m16n8k8.row.col.f32.tf32.tf32.f32 "
    "{%0,%1,%2,%3}, {%4,%5,%6,%7}, {%8,%9}, {%0,%1,%2,%3};"
    : "+f"(d[0]), "+f"(d[1]), "+f"(d[2]), "+f"(d[3])
    : "r"(a[0]), "r"(a[1]), "r"(a[2]), "r"(a[3]), "r"(b[0]), "r"(b[1]));
}
#define DOT4(acc, a, b) acc = fmaf((a).x,(b).x, fmaf((a).y,(b).y, fmaf((a).z,(b).z, fmaf((a).w,(b).w,(acc)))))

// fast LSTM cell: 5 EX2 + 2 RCP per element (grouped reciprocal)
__device__ __forceinline__ void lstm_cell(float gi, float gf, float gg, float go,
                                          float& c, float& hn){
  gi = fminf(fmaxf(gi, -15.f), 15.f);
  gf = fminf(fmaxf(gf, -15.f), 15.f);
  gg = fminf(fmaxf(gg, -15.f), 15.f);
  go = fminf(fmaxf(go, -15.f), 15.f);
  float ei = __expf(-gi), ef = __expf(-gf), eo = __expf(-go), eg = __expf(-2.f*gg);
  float di = 1.f+ei, df = 1.f+ef, dv = 1.f+eo, dg = 1.f+eg;
  float q1 = di*df, q2 = dv*dg;
  float rp = __fdividef(1.f, q1*q2);
  float si = rp*df*q2;              // sigmoid(gi)
  float sf = rp*di*q2;              // sigmoid(gf)
  float so = rp*q1*dg;              // sigmoid(go)
  float tg = (1.f-eg)*(rp*q1*dv);   // tanh(gg)
  float cn = fmaf(sf, c, si*tg);
  c = cn;
  float tc = fminf(fmaxf(cn, -15.f), 15.f);
  float ec = __expf(-2.f*tc);
  hn = so * (1.f-ec) * __fdividef(1.f, 1.f+ec);
}

// ---------------- prologue 1: E2 = embed @ Wih_emb^T ----------------
__global__ void __launch_bounds__(256) k_E(const float* __restrict__ emb,
                                           const float* __restrict__ Wih){
  __shared__ float As[16*68], Bs[16*68];
  const int tid = threadIdx.x;
  const int tx = tid & 15, ty = tid >> 4;
  const int c0 = blockIdx.x * 64, v0 = blockIdx.y * 64;
  float acc[4][4];
#pragma unroll
  for (int i=0;i<4;++i)
#pragma unroll
    for (int j=0;j<4;++j) acc[i][j] = 0.f;

  const int rr = tid >> 2, kq = tid & 3;
  for (int kc = 0; kc < 512; kc += 16){
    int v = v0 + rr; if (v >= VOCAB_) v = VOCAB_ - 1;
    float4 a = __ldg((const float4*)(emb + (size_t)v*512 + kc + 4*kq));
    As[(4*kq+0)*68 + rr] = a.x; As[(4*kq+1)*68 + rr] = a.y;
    As[(4*kq+2)*68 + rr] = a.z; As[(4*kq+3)*68 + rr] = a.w;
    int g = c0 + rr;
    float4 b = __ldg((const float4*)(Wih + (size_t)g*1024 + 512 + kc + 4*kq));
    Bs[(4*kq+0)*68 + rr] = b.x; Bs[(4*kq+1)*68 + rr] = b.y;
    Bs[(4*kq+2)*68 + rr] = b.z; Bs[(4*kq+3)*68 + rr] = b.w;
    __syncthreads();
#pragma unroll
    for (int k = 0; k < 16; ++k){
      float4 av = *(const float4*)&As[k*68 + ty*4];
      float4 bv = *(const float4*)&Bs[k*68 + tx*4];
      float ai[4] = {av.x, av.y, av.z, av.w};
      float bj[4] = {bv.x, bv.y, bv.z, bv.w};
#pragma unroll
      for (int i=0;i<4;++i)
#pragma unroll
        for (int j=0;j<4;++j) acc[i][j] = fmaf(ai[i], bj[j], acc[i][j]);
    }
    __syncthreads();
  }
  for (int i=0;i<4;++i){
    int v = v0 + ty*4 + i;
    if (v < VOCAB_)
      for (int j=0;j<4;++j){
        int c = c0 + tx*4 + j;
        g_E2[((size_t)v*512 + (c & 511))*4 + (c >> 9)] = acc[i][j];
      }
  }
}

// ---------------- prologue 2: g_base (exact fp32) ----------------
__global__ void __launch_bounds__(256) k_base(const float* __restrict__ Wih,
                                              const float* __restrict__ bih,
                                              const float* __restrict__ bhh,
                                              const float* __restrict__ ctx){
  __shared__ float xs[128*68], wsm[16*68];
  const int tid = threadIdx.x, blk = blockIdx.x;
  const int tx = tid & 7, ty = tid >> 3, r0 = ty*4;
  const int gc0 = blk*16 + 2*tx, gc1 = gc0 + 1;
  float acc[4][2];
#pragma unroll
  for (int i=0;i<4;++i){ acc[i][0]=0.f; acc[i][1]=0.f; }

  for (int kc = 0; kc < 512; kc += 64){
    for (int p = 0; p < 8; ++p){
      int lin = tid + p*256; int r = lin >> 4, kq2 = lin & 15;
      *(float4*)&xs[r*68 + 4*kq2] = __ldg((const float4*)(ctx + (size_t)r*512 + kc + 4*kq2));
    }
    { int cc = tid >> 4, kq2 = tid & 15;
      *(float4*)&wsm[cc*68 + 4*kq2] =
        __ldg((const float4*)(Wih + (size_t)(blk*16+cc)*1024 + kc + 4*kq2)); }
    __syncthreads();
#pragma unroll
    for (int k4 = 0; k4 < 16; ++k4){
      int kl = 4*k4;
      float4 w0 = *(const float4*)&wsm[(2*tx)*68 + kl];
      float4 w1 = *(const float4*)&wsm[(2*tx+1)*68 + kl];
#pragma unroll
      for (int i=0;i<4;++i){
        float4 h4 = *(const float4*)&xs[(r0+i)*68 + kl];
        DOT4(acc[i][0], h4, w0); DOT4(acc[i][1], h4, w1);
      }
    }
    __syncthreads();
  }
  float bb0 = __ldg(bih+gc0) + __ldg(bhh+gc0);
  float bb1 = __ldg(bih+gc1) + __ldg(bhh+gc1);
  for (int i=0;i<4;++i){
    g_base[(size_t)gc0*B_ + r0+i] = acc[i][0] + bb0;
    g_base[(size_t)gc1*B_ + r0+i] = acc[i][1] + bb1;
  }
}

// ---------------- prologue 3 ----------------
__global__ void k_init(const float* __restrict__ ctx, const int* __restrict__ sid){
  int idx = blockIdx.x*blockDim.x + threadIdx.x;
  if (idx < B_*HID_){
    float x = ctx[idx];
    float hi = tf32_rd(x);
    g_hhi[idx] = hi;
    g_hlo[idx] = tf32_rd(x - hi);
  }
  if (idx < B_){
    g_pack[0][idx] = (unsigned long long)(unsigned)((VOCAB_-1) - *sid);
    g_pack[1][idx] = 0ull;
    g_done[0][idx] = 0u;
    g_done[1][idx] = 0u;
  }
  if (idx == 0) g_bar = 0u;
}

// ---------------- grid barrier ----------------
__device__ __forceinline__ void gbar(unsigned target){
  __syncthreads();
  if (threadIdx.x == 0){
    __threadfence();
    atomicAdd(&g_bar, 1u);
    while (*(volatile unsigned*)&g_bar < target) { }
    __threadfence();
  }
  __syncthreads();
}

// ---------------- persistent kernel ----------------
// smem float offsets
#define SA_H   0                 // A hi frag-packed: 96*128 = 12288
#define SA_L   12288             // A lo
#define SB_H   24576             // B hi tile [128][68] = 8704
#define SB_L   33280             // B lo tile
#define S_LS   41984             // 8*128 floats
#define SMW_   43008             // 172032 bytes

__global__ void __launch_bounds__(NTHR, 1)
k_persist(const float* __restrict__ Whh, const float* __restrict__ Wout,
          const float* __restrict__ bout, float* __restrict__ out){
  extern __shared__ float sm[];
  float* Ah = sm + SA_H;
  float* Al = sm + SA_L;
  float* Bh = sm + SB_H;
  float* Bl = sm + SB_L;
  float* Ls = sm + S_LS;

  const int cta = blockIdx.x, tid = threadIdx.x;
  const int wid = tid >> 5, lane = tid & 31;
  const bool isX = (cta < XCTAS);
  const int mtile = cta >> 2, kidx = cta & 3, kbase = kidx*128;
  const int wm = wid >> 2, wn = wid & 3;          // warp tile 48M x 32N

  // ---- stage A (weights hi/lo, fragment-packed) once ----
  if (isX){
    for (int lin = tid; lin < 3072; lin += NTHR){
      int ml = lin >> 5, q = lin & 31;
      int gm = mtile*96 + ml;
      float4 w = make_float4(0.f,0.f,0.f,0.f);
      if (gm < NG_)        w = __ldg((const float4*)(Whh  + (size_t)gm*HID_ + kbase + q*4));
      else if (gm < VTOT_) w = __ldg((const float4*)(Wout + (size_t)(gm-NG_)*HID_ + kbase + q*4));
      int f = (ml >> 4)*16 + (q >> 1);
      int ofs = f*128 + (ml & 7)*16 + ((ml >> 3) & 1) + 2*(q & 1);
      float hi;
      hi = tf32_rd(w.x); Ah[ofs+ 0] = hi; Al[ofs+ 0] = tf32_rd(w.x - hi);
      hi = tf32_rd(w.y); Ah[ofs+ 4] = hi; Al[ofs+ 4] = tf32_rd(w.y - hi);
      hi = tf32_rd(w.z); Ah[ofs+ 8] = hi; Al[ofs+ 8] = tf32_rd(w.z - hi);
      hi = tf32_rd(w.w); Ah[ofs+12] = hi; Al[ofs+12] = tf32_rd(w.w - hi);
    }
  }
  __syncthreads();

  float cr0 = 0.f, cr1 = 0.f;
  const int yi0 = cta*NTHR + tid;                 // < 37888
  const int yi1 = yi0 + GRID_*NTHR;               // yi1 & 127 == yi0 & 127
  const bool v1ok = (yi1 < B_*HID_);

  unsigned bt = 0;
  for (int m = 0; m <= T_; ++m){
    // ================ phase X: 3xTF32 mma.sync ================
    if (isX){
      float acc[12][4];
#pragma unroll
      for (int i=0;i<12;++i)
#pragma unroll
        for (int j=0;j<4;++j) acc[i][j] = 0.f;

      for (int ch = 0; ch < 2; ++ch){
        for (int lin = tid; lin < 2048; lin += NTHR){
          int r = lin >> 4, q = lin & 15;
          float4 h = __ldcg((const float4*)(g_hhi + (size_t)r*HID_ + kbase + ch*64 + q*4));
          float4 l = __ldcg((const float4*)(g_hlo + (size_t)r*HID_ + kbase + ch*64 + q*4));
          *(float4*)&Bh[r*68 + q*4] = h;
          *(float4*)&Bl[r*68 + q*4] = l;
        }
        __syncthreads();
#pragma unroll 2
        for (int ks = 0; ks < 8; ++ks){
          uint32_t bh[4][2], bl[4][2];
          int kk = ks*8 + (lane & 3);
#pragma unroll
          for (int ni = 0; ni < 4; ++ni){
            int n = wn*32 + ni*8 + (lane >> 2);
            bh[ni][0] = __float_as_uint(Bh[n*68 + kk]);
            bh[ni][1] = __float_as_uint(Bh[n*68 + kk + 4]);
            bl[ni][0] = __float_as_uint(Bl[n*68 + kk]);
            bl[ni][1] = __float_as_uint(Bl[n*68 + kk + 4]);
          }
#pragma unroll
          for (int mi = 0; mi < 3; ++mi){
            int f = (wm*3 + mi)*16 + ch*8 + ks;
            uint4 ahv = *(const uint4*)&Ah[(f*32 + lane)*4];
            uint4 alv = *(const uint4*)&Al[(f*32 + lane)*4];
            const uint32_t* ah = (const uint32_t*)&ahv;
            const uint32_t* al = (const uint32_t*)&alv;
#pragma unroll
            for (int ni = 0; ni < 4; ++ni){
              mma_tf32(acc[mi*4+ni], ah, bh[ni]);
              mma_tf32(acc[mi*4+ni], ah, bl[ni]);
              mma_tf32(acc[mi*4+ni], al, bh[ni]);
            }
          }
        }
        __syncthreads();
      }
#pragma unroll
      for (int mi = 0; mi < 3; ++mi){
#pragma unroll
        for (int ni = 0; ni < 4; ++ni){
          int row0 = mtile*96 + wm*48 + mi*16 + (lane >> 2);
          int col = wn*32 + ni*8 + (lane & 3)*2;
          float* dst = g_part + ((size_t)kidx*ROWS_ + row0)*B_ + col;
          *(float2*)dst = make_float2(acc[mi*4+ni][0], acc[mi*4+ni][1]);
          *(float2*)(dst + 8*B_) = make_float2(acc[mi*4+ni][2], acc[mi*4+ni][3]);
        }
      }
    }
    bt += GRID_; gbar(bt);

    // ========== fused region: Yv (vocab+argmax+signal) + Yc (spin+cell) ====
    // resets for next step's buffers (consumed >= 1 barrier later)
    if (m < T_ && yi0 < B_){
      g_pack[(m+1) & 1][yi0] = 0ull;
      g_done[(m+1) & 1][yi0] = 0u;
    }
    if (m >= 1){
      const int v0 = cta*7;
      if (wid < 7){
        int v = v0 + wid;
        if (v < VOCAB_){
          float bo = __ldg(bout + v);
          const float* p = g_part + (size_t)(NG_ + v)*B_;
#pragma unroll
          for (int rq = 0; rq < 4; ++rq){
            int r = rq*32 + lane;
            float sum = bo + __ldcg(p + r)
                      + __ldcg(p + (size_t)ROWS_*B_ + r)
                      + __ldcg(p + (size_t)2*ROWS_*B_ + r)
                      + __ldcg(p + (size_t)3*ROWS_*B_ + r);
            Ls[wid*128 + r] = sum;
          }
        }
      }
      __syncthreads();
      // argmax contribution + per-row completion signal (ASAP, all 148 CTAs)
      if (m < T_ && tid < 128){
        int r = tid;
        unsigned long long best = 0ull;
        for (int vl = 0; vl < 7; ++vl){
          int v = v0 + vl;
          if (v < VOCAB_){
            unsigned long long pk = ((unsigned long long)fkey(Ls[vl*128 + r]) << 32)
                                  | (unsigned)(VOCAB_-1 - v);
            if (pk > best) best = pk;
          }
        }
        if (best) atomicMax(&g_pack[m & 1][r], best);
        __threadfence();
        atomicAdd(&g_done[m & 1][r], 1u);
      }
      // logits store (off the critical path)
      for (int it = tid; it < 128*8; it += NTHR){
        int r = it >> 3, vl = it & 7;
        int v = v0 + vl;
        if (vl < 7 && v < VOCAB_)
          out[((size_t)r*T_ + (m-1))*VOCAB_ + v] = Ls[vl*128 + r];
      }
    }
    if (m == T_) break;

    // ---- Yc: prefetch token-independent gates, spin, cell ----
    {
      const int r = yi0 & 127;
      const int u0 = yi0 >> 7, u1 = yi1 >> 7;
      float A0[4], A1[4];
#pragma unroll
      for (int g = 0; g < 4; ++g){
        size_t c0 = (size_t)(g*512 + u0)*B_ + r;
        A0[g] = g_base[c0] + __ldcg(&g_part[c0]) + __ldcg(&g_part[(size_t)ROWS_*B_ + c0])
              + __ldcg(&g_part[(size_t)2*ROWS_*B_ + c0]) + __ldcg(&g_part[(size_t)3*ROWS_*B_ + c0]);
      }
      if (v1ok){
#pragma unroll
        for (int g = 0; g < 4; ++g){
          size_t c1 = (size_t)(g*512 + u1)*B_ + r;
          A1[g] = g_base[c1] + __ldcg(&g_part[c1]) + __ldcg(&g_part[(size_t)ROWS_*B_ + c1])
                + __ldcg(&g_part[(size_t)2*ROWS_*B_ + c1]) + __ldcg(&g_part[(size_t)3*ROWS_*B_ + c1]);
        }
      }
      if (m >= 1){
        volatile unsigned* dc = (volatile unsigned*)g_done[m & 1];
        while (dc[r] < (unsigned)GRID_) { __nanosleep(32); }
        __threadfence();
      }
      unsigned long long p = __ldcg(&g_pack[m & 1][r]);
      int tok = (VOCAB_-1) - (int)(unsigned)(p & 0xffffffffull);
      {
        float4 ev = __ldg((const float4*)&g_E2[((size_t)tok*HID_ + u0)*4]);
        float hn;
        lstm_cell(A0[0]+ev.x, A0[1]+ev.y, A0[2]+ev.z, A0[3]+ev.w, cr0, hn);
        float hi = tf32_rd(hn);
        g_hhi[(size_t)r*HID_ + u0] = hi;
        g_hlo[(size_t)r*HID_ + u0] = tf32_rd(hn - hi);
        if (m == T_-1){
          out[OUT_H + (size_t)r*HID_ + u0] = hn;
          out[OUT_C + (size_t)r*HID_ + u0] = cr0;
        }
      }
      if (v1ok){
        float4 ev = __ldg((const float4*)&g_E2[((size_t)tok*HID_ + u1)*4]);
        float hn;
        lstm_cell(A1[0]+ev.x, A1[1]+ev.y, A1[2]+ev.z, A1[3]+ev.w, cr1, hn);
        float hi = tf32_rd(hn);
        g_hhi[(size_t)r*HID_ + u1] = hi;
        g_hlo[(size_t)r*HID_ + u1] = tf32_rd(hn - hi);
        if (m == T_-1){
          out[OUT_H + (size_t)r*HID_ + u1] = hn;
          out[OUT_C + (size_t)r*HID_ + u1] = cr1;
        }
      }
    }
    bt += GRID_; gbar(bt);
  }
}

// ---------------- launch ----------------
extern "C" void kernel_launch(void* const* d_in, const int* in_sizes, int n_in,
                              void* d_out, int out_size){
  const float* ctx  = (const float*)d_in[0];
  const float* emb  = (const float*)d_in[1];
  const float* Wih  = (const float*)d_in[2];
  const float* bih  = (const float*)d_in[3];
  const float* Whh  = (const float*)d_in[4];
  const float* bhh  = (const float*)d_in[5];
  const float* Wout = (const float*)d_in[6];
  const float* bout = (const float*)d_in[7];
  const int*   sid  = (const int*)d_in[8];
  float* out = (float*)d_out;

  cudaFuncSetAttribute(k_persist, cudaFuncAttributeMaxDynamicSharedMemorySize,
                       SMW_ * 4);

  dim3 gE(32, 16);
  k_E<<<gE, 256>>>(emb, Wih);
  k_base<<<128, 256>>>(Wih, bih, bhh, ctx);
  k_init<<<256, 256>>>(ctx, sid);
  k_persist<<<GRID_, NTHR, SMW_ * 4>>>(Whh, Wout, bout, out);
}